// round 1
// baseline (speedup 1.0000x reference)
#include <cuda_runtime.h>
#include <cuda_bf16.h>
#include <cstdint>

#define QT 16384
#define ST 16384
#define DD 1024
#define NL 64

// ---- scratch (device globals; no allocation allowed) ----
__device__ float          g_proto[NL * DD];
__device__ float          g_counts[NL];
__device__ __nv_bfloat16  g_protobf[NL * DD];
__device__ float          g_p2[NL];

// ============================================================
// k_zero: zero proto accumulator + counts
// ============================================================
__global__ void k_zero() {
    int i = blockIdx.x * 256 + threadIdx.x;
    if (i < NL * DD) g_proto[i] = 0.f;
    if (i < NL)      g_counts[i] = 0.f;
}

// ============================================================
// k_acc: masked scatter-add of support embeddings into prototypes.
// grid (32 dim-chunks of 32, 8 token tiles of 2048), 128 threads (4 warps).
// Warp-private shared accumulators -> no shared atomics in hot loop.
// ============================================================
__global__ void __launch_bounds__(128) k_acc(const float* __restrict__ emb,
                                             const int* __restrict__ tag,
                                             const int* __restrict__ msk) {
    __shared__ float acc[4][NL][32];   // 32 KB
    __shared__ float cs[4][NL];        // 1 KB (counts, chunk 0 only)
    int t = threadIdx.x, w = t >> 5, l = t & 31;
    int chunk = blockIdx.x;            // 0..31
    int base  = blockIdx.y * 2048;

    for (int i = t; i < 4 * NL * 32; i += 128) ((float*)acc)[i] = 0.f;
    for (int i = t; i < 4 * NL; i += 128)      ((float*)cs)[i]  = 0.f;
    __syncthreads();

    #pragma unroll 2
    for (int i = w; i < 2048; i += 4) {
        int tk = base + i;
        int tg = __ldg(tag + tk);      // uniform per warp (broadcast)
        int mk = __ldg(msk + tk);
        if (mk) {                      // whole-warp skip -> saves HBM lines
            float v = __ldg(emb + (size_t)tk * DD + chunk * 32 + l);
            acc[w][tg][l] += v;        // bank l: conflict-free, warp-private
            if (chunk == 0 && l == 0) cs[w][tg] += 1.f;
        }
    }
    __syncthreads();

    for (int idx = t; idx < NL * 32; idx += 128) {
        int n = idx >> 5, d2 = idx & 31;
        float s = acc[0][n][d2] + acc[1][n][d2] + acc[2][n][d2] + acc[3][n][d2];
        atomicAdd(&g_proto[n * DD + chunk * 32 + d2], s);
    }
    if (chunk == 0) {
        for (int n = t; n < NL; n += 128) {
            float s = cs[0][n] + cs[1][n] + cs[2][n] + cs[3][n];
            atomicAdd(&g_counts[n], s);
        }
    }
}

// ============================================================
// k_fin: proto /= max(count,1); emit bf16 proto + fp32 p2.
// grid 64 (one block per label), 256 threads.
// ============================================================
__global__ void k_fin() {
    int n = blockIdx.x, t = threadIdx.x;
    float inv = 1.f / fmaxf(g_counts[n], 1.f);
    float ps = 0.f;
    for (int d = t; d < DD; d += 256) {
        float v = g_proto[n * DD + d] * inv;
        g_protobf[n * DD + d] = __float2bfloat16_rn(v);
        ps += v * v;
    }
    for (int o = 16; o; o >>= 1) ps += __shfl_xor_sync(0xffffffffu, ps, o);
    __shared__ float red[8];
    if ((t & 31) == 0) red[t >> 5] = ps;
    __syncthreads();
    if (t == 0) {
        float s = 0.f;
        #pragma unroll
        for (int i = 0; i < 8; i++) s += red[i];
        g_p2[n] = s;
    }
}

// ============================================================
// k_main: logits[qt][n] = -(q2 + p2 - 2*dot(q,proto)) * qmask
// Block: 64 query tokens x all 64 protos. 128 threads (4 warps).
// Warp w: m-rows [ (w>>1)*32, +32 ), n-cols [ (w&1)*32, +32 )
// -> per warp 2 m16 tiles x 4 n8 tiles, mma.m16n8k16 bf16, fp32 acc.
// q2 accumulated in fp32 registers from the SAME loads feeding bf16.
// ============================================================
__global__ void __launch_bounds__(128) k_main(const float* __restrict__ q,
                                              const int* __restrict__ qmsk,
                                              float* __restrict__ out) {
    __shared__ __nv_bfloat16 q_sh[64][72];   // pad 8 bf16 -> conflict-free frags
    __shared__ __nv_bfloat16 p_sh[64][72];
    __shared__ float q2_sh[64], p2_sh[64];
    __shared__ int   msk_sh[64];

    int t = threadIdx.x;
    int tok0 = blockIdx.x * 64;
    if (t < 64) { p2_sh[t] = g_p2[t]; msk_sh[t] = qmsk[tok0 + t]; }

    int warp = t >> 5, l = t & 31;
    int wm = warp >> 1, wn = warp & 1;
    int g = l >> 2, kb = (l & 3) * 2;
    int lt = t >> 4, kv = t & 15;       // q loader: 16 thr per token row
    int prow = t >> 3, pcol = t & 7;    // proto loader

    float acc[2][4][4];
    #pragma unroll
    for (int a = 0; a < 2; a++)
        #pragma unroll
        for (int b = 0; b < 4; b++)
            #pragma unroll
            for (int cc = 0; cc < 4; cc++) acc[a][b][cc] = 0.f;
    float q2p[8] = {0.f,0.f,0.f,0.f,0.f,0.f,0.f,0.f};

    for (int c = 0; c < 16; c++) {
        // ---- stage query chunk (fp32 read once: q2 + bf16 convert) ----
        #pragma unroll
        for (int p = 0; p < 8; p++) {
            int tl = p * 8 + lt;
            float4 v = *reinterpret_cast<const float4*>(
                q + (size_t)(tok0 + tl) * DD + c * 64 + kv * 4);
            q2p[p] += v.x * v.x + v.y * v.y + v.z * v.z + v.w * v.w;
            __nv_bfloat162 h0 = __floats2bfloat162_rn(v.x, v.y);
            __nv_bfloat162 h1 = __floats2bfloat162_rn(v.z, v.w);
            uint2 u;
            u.x = reinterpret_cast<unsigned&>(h0);
            u.y = reinterpret_cast<unsigned&>(h1);
            *reinterpret_cast<uint2*>(&q_sh[tl][kv * 4]) = u;
        }
        // ---- stage proto chunk (bf16, L2-resident) ----
        #pragma unroll
        for (int p = 0; p < 4; p++) {
            int r = p * 16 + prow;
            *reinterpret_cast<uint4*>(&p_sh[r][pcol * 8]) =
                *reinterpret_cast<const uint4*>(&g_protobf[r * DD + c * 64 + pcol * 8]);
        }
        __syncthreads();

        #pragma unroll
        for (int s = 0; s < 4; s++) {
            int k0 = s * 16 + kb;
            unsigned a[2][4], b[4][2];
            #pragma unroll
            for (int mt = 0; mt < 2; mt++) {
                int r = wm * 32 + mt * 16 + g;
                a[mt][0] = *reinterpret_cast<const unsigned*>(&q_sh[r][k0]);
                a[mt][1] = *reinterpret_cast<const unsigned*>(&q_sh[r + 8][k0]);
                a[mt][2] = *reinterpret_cast<const unsigned*>(&q_sh[r][k0 + 8]);
                a[mt][3] = *reinterpret_cast<const unsigned*>(&q_sh[r + 8][k0 + 8]);
            }
            #pragma unroll
            for (int nt = 0; nt < 4; nt++) {
                int n0 = wn * 32 + nt * 8 + g;
                b[nt][0] = *reinterpret_cast<const unsigned*>(&p_sh[n0][k0]);
                b[nt][1] = *reinterpret_cast<const unsigned*>(&p_sh[n0][k0 + 8]);
            }
            #pragma unroll
            for (int mt = 0; mt < 2; mt++)
                #pragma unroll
                for (int nt = 0; nt < 4; nt++)
                    asm volatile(
                        "mma.sync.aligned.m16n8k16.row.col.f32.bf16.bf16.f32 "
                        "{%0,%1,%2,%3}, {%4,%5,%6,%7}, {%8,%9}, {%0,%1,%2,%3};\n"
                        : "+f"(acc[mt][nt][0]), "+f"(acc[mt][nt][1]),
                          "+f"(acc[mt][nt][2]), "+f"(acc[mt][nt][3])
                        : "r"(a[mt][0]), "r"(a[mt][1]), "r"(a[mt][2]), "r"(a[mt][3]),
                          "r"(b[nt][0]), "r"(b[nt][1]));
        }
        __syncthreads();
    }

    // ---- fold per-thread q2 partials (16 lanes per token) ----
    #pragma unroll
    for (int p = 0; p < 8; p++) {
        float v = q2p[p];
        v += __shfl_xor_sync(0xffffffffu, v, 8);
        v += __shfl_xor_sync(0xffffffffu, v, 4);
        v += __shfl_xor_sync(0xffffffffu, v, 2);
        v += __shfl_xor_sync(0xffffffffu, v, 1);
        if (kv == 0) q2_sh[p * 8 + lt] = v;
    }
    __syncthreads();

    // ---- epilogue ----
    #pragma unroll
    for (int mt = 0; mt < 2; mt++) {
        int r0 = wm * 32 + mt * 16 + g;
        int r1 = r0 + 8;
        float m0 = (float)msk_sh[r0], m1 = (float)msk_sh[r1];
        float q20 = q2_sh[r0], q21 = q2_sh[r1];
        #pragma unroll
        for (int nt = 0; nt < 4; nt++) {
            int cc = wn * 32 + nt * 8 + kb;
            float p20 = p2_sh[cc], p21 = p2_sh[cc + 1];
            float2 o0, o1;
            o0.x = -(q20 + p20 - 2.f * acc[mt][nt][0]) * m0;
            o0.y = -(q20 + p21 - 2.f * acc[mt][nt][1]) * m0;
            o1.x = -(q21 + p20 - 2.f * acc[mt][nt][2]) * m1;
            o1.y = -(q21 + p21 - 2.f * acc[mt][nt][3]) * m1;
            *reinterpret_cast<float2*>(out + (size_t)(tok0 + r0) * NL + cc) = o0;
            *reinterpret_cast<float2*>(out + (size_t)(tok0 + r1) * NL + cc) = o1;
        }
    }
}

// ============================================================
extern "C" void kernel_launch(void* const* d_in, const int* in_sizes, int n_in,
                              void* d_out, int out_size) {
    const float* s_emb = (const float*)d_in[0];
    const int*   s_tag = (const int*)d_in[1];
    const int*   s_msk = (const int*)d_in[2];
    const float* q_emb = (const float*)d_in[3];
    const int*   q_msk = (const int*)d_in[4];
    float* out = (float*)d_out;

    k_zero<<<256, 256>>>();
    dim3 ga(32, 8);
    k_acc<<<ga, 128>>>(s_emb, s_tag, s_msk);
    k_fin<<<64, 256>>>();
    k_main<<<256, 128>>>(q_emb, q_msk, out);
}

// round 3
// speedup vs baseline: 3.1486x; 3.1486x over previous
#include <cuda_runtime.h>
#include <cuda_bf16.h>
#include <cstdint>

#define QT 16384
#define ST 16384
#define DD 1024
#define NL 64
#define NW 8   // warps in k_acc block

// ---- scratch (device globals; no allocation allowed) ----
__device__ float          g_proto[NL * DD];
__device__ float          g_counts[NL];
__device__ __nv_bfloat16  g_protobf[NL * DD];
__device__ float          g_p2[NL];

// ============================================================
// k_zero
// ============================================================
__global__ void k_zero() {
    int i = blockIdx.x * 256 + threadIdx.x;
    if (i < NL * DD) g_proto[i] = 0.f;
    if (i < NL)      g_counts[i] = 0.f;
}

// ============================================================
// k_acc: masked scatter-add, 8 warps, warp-private shared acc,
// token loop unrolled x8 for MLP on the DRAM loads.
// grid (32 dim-chunks, 8 token tiles of 2048), 256 threads.
// ============================================================
__global__ void __launch_bounds__(256) k_acc(const float* __restrict__ emb,
                                             const int* __restrict__ tag,
                                             const int* __restrict__ msk) {
    __shared__ float acc[NW][NL][32];   // 64 KB
    __shared__ float cs[NW][NL];        // 2 KB
    int t = threadIdx.x, w = t >> 5, l = t & 31;
    int chunk = blockIdx.x;             // 0..31
    int base  = blockIdx.y * 2048;

    for (int i = t; i < NW * NL * 32; i += 256) ((float*)acc)[i] = 0.f;
    for (int i = t; i < NW * NL; i += 256)      ((float*)cs)[i]  = 0.f;
    __syncthreads();

    #pragma unroll 1
    for (int j = w; j < 2048; j += NW * 8) {
        int tg[8], mk[8]; float v[8];
        #pragma unroll
        for (int u = 0; u < 8; u++) {
            int tk = base + j + u * NW;
            tg[u] = __ldg(tag + tk);
            mk[u] = __ldg(msk + tk);
        }
        #pragma unroll
        for (int u = 0; u < 8; u++) {
            int tk = base + j + u * NW;
            v[u] = mk[u] ? __ldg(emb + (size_t)tk * DD + chunk * 32 + l) : 0.f;
        }
        #pragma unroll
        for (int u = 0; u < 8; u++) {
            if (mk[u]) {
                acc[w][tg[u]][l] += v[u];
                if (chunk == 0 && l == 0) cs[w][tg[u]] += 1.f;
            }
        }
    }
    __syncthreads();

    for (int idx = t; idx < NL * 32; idx += 256) {
        int n = idx >> 5, d2 = idx & 31;
        float s = 0.f;
        #pragma unroll
        for (int w2 = 0; w2 < NW; w2++) s += acc[w2][n][d2];
        atomicAdd(&g_proto[n * DD + chunk * 32 + d2], s);
    }
    if (chunk == 0) {
        for (int n = t; n < NL; n += 256) {
            float s = 0.f;
            #pragma unroll
            for (int w2 = 0; w2 < NW; w2++) s += cs[w2][n];
            atomicAdd(&g_counts[n], s);
        }
    }
}

// ============================================================
// k_fin: proto /= max(count,1); emit bf16 proto + fp32 p2.
// ============================================================
__global__ void k_fin() {
    int n = blockIdx.x, t = threadIdx.x;
    float inv = 1.f / fmaxf(g_counts[n], 1.f);
    float ps = 0.f;
    for (int d = t; d < DD; d += 256) {
        float v = g_proto[n * DD + d] * inv;
        g_protobf[n * DD + d] = __float2bfloat16_rn(v);
        ps += v * v;
    }
    for (int o = 16; o; o >>= 1) ps += __shfl_xor_sync(0xffffffffu, ps, o);
    __shared__ float red[8];
    if ((t & 31) == 0) red[t >> 5] = ps;
    __syncthreads();
    if (t == 0) {
        float s = 0.f;
        #pragma unroll
        for (int i = 0; i < 8; i++) s += red[i];
        g_p2[n] = s;
    }
}

// ============================================================
// k_main: software-pipelined, double-buffered shared.
// Block: 64 tokens x 64 protos, 128 threads (4 warps).
// ============================================================
__global__ void __launch_bounds__(128, 4) k_main(const float* __restrict__ q,
                                                 const int* __restrict__ qmsk,
                                                 float* __restrict__ out) {
    __shared__ __nv_bfloat16 q_sh[2][64][72];
    __shared__ __nv_bfloat16 p_sh[2][64][72];
    __shared__ float q2_sh[64], p2_sh[64];
    __shared__ int   msk_sh[64];

    int t = threadIdx.x;
    int tok0 = blockIdx.x * 64;
    if (t < 64) { p2_sh[t] = g_p2[t]; msk_sh[t] = qmsk[tok0 + t]; }

    int warp = t >> 5, l = t & 31;
    int wm = warp >> 1, wn = warp & 1;
    int g = l >> 2, kb = (l & 3) * 2;
    int lt = t >> 4, kv = t & 15;       // q loader lane mapping
    int prow = t >> 3, pcol = t & 7;    // proto loader lane mapping

    const float* qbase = q + (size_t)tok0 * DD;

    float acc[2][4][4];
    #pragma unroll
    for (int a = 0; a < 2; a++)
        #pragma unroll
        for (int b = 0; b < 4; b++)
            #pragma unroll
            for (int cc = 0; cc < 4; cc++) acc[a][b][cc] = 0.f;
    float q2p[8] = {0.f,0.f,0.f,0.f,0.f,0.f,0.f,0.f};

    float4 v[8];
    uint4  pv[4];

    auto load_chunk = [&](int c) {
        #pragma unroll
        for (int p = 0; p < 8; p++)
            v[p] = *reinterpret_cast<const float4*>(
                qbase + (size_t)(p * 8 + lt) * DD + c * 64 + kv * 4);
        #pragma unroll
        for (int p = 0; p < 4; p++)
            pv[p] = *reinterpret_cast<const uint4*>(
                &g_protobf[(p * 16 + prow) * DD + c * 64 + pcol * 8]);
    };
    auto store_chunk = [&](int buf) {
        #pragma unroll
        for (int p = 0; p < 8; p++) {
            q2p[p] += v[p].x * v[p].x + v[p].y * v[p].y
                    + v[p].z * v[p].z + v[p].w * v[p].w;
            __nv_bfloat162 h0 = __floats2bfloat162_rn(v[p].x, v[p].y);
            __nv_bfloat162 h1 = __floats2bfloat162_rn(v[p].z, v[p].w);
            uint2 u;
            u.x = reinterpret_cast<unsigned&>(h0);
            u.y = reinterpret_cast<unsigned&>(h1);
            *reinterpret_cast<uint2*>(&q_sh[buf][p * 8 + lt][kv * 4]) = u;
        }
        #pragma unroll
        for (int p = 0; p < 4; p++)
            *reinterpret_cast<uint4*>(&p_sh[buf][p * 16 + prow][pcol * 8]) = pv[p];
    };

    load_chunk(0);
    store_chunk(0);

    for (int c = 0; c < 16; c++) {
        __syncthreads();
        if (c < 15) load_chunk(c + 1);      // LDGs in flight during MMAs
        int cb = c & 1;
        #pragma unroll
        for (int s = 0; s < 4; s++) {
            int k0 = s * 16 + kb;
            unsigned a[2][4], b[4][2];
            #pragma unroll
            for (int mt = 0; mt < 2; mt++) {
                int r = wm * 32 + mt * 16 + g;
                a[mt][0] = *reinterpret_cast<const unsigned*>(&q_sh[cb][r][k0]);
                a[mt][1] = *reinterpret_cast<const unsigned*>(&q_sh[cb][r + 8][k0]);
                a[mt][2] = *reinterpret_cast<const unsigned*>(&q_sh[cb][r][k0 + 8]);
                a[mt][3] = *reinterpret_cast<const unsigned*>(&q_sh[cb][r + 8][k0 + 8]);
            }
            #pragma unroll
            for (int nt = 0; nt < 4; nt++) {
                int n0 = wn * 32 + nt * 8 + g;
                b[nt][0] = *reinterpret_cast<const unsigned*>(&p_sh[cb][n0][k0]);
                b[nt][1] = *reinterpret_cast<const unsigned*>(&p_sh[cb][n0][k0 + 8]);
            }
            #pragma unroll
            for (int mt = 0; mt < 2; mt++)
                #pragma unroll
                for (int nt = 0; nt < 4; nt++)
                    asm volatile(
                        "mma.sync.aligned.m16n8k16.row.col.f32.bf16.bf16.f32 "
                        "{%0,%1,%2,%3}, {%4,%5,%6,%7}, {%8,%9}, {%0,%1,%2,%3};\n"
                        : "+f"(acc[mt][nt][0]), "+f"(acc[mt][nt][1]),
                          "+f"(acc[mt][nt][2]), "+f"(acc[mt][nt][3])
                        : "r"(a[mt][0]), "r"(a[mt][1]), "r"(a[mt][2]), "r"(a[mt][3]),
                          "r"(b[nt][0]), "r"(b[nt][1]));
        }
        if (c < 15) store_chunk((c + 1) & 1);
    }

    // ---- fold per-thread q2 partials (16 lanes per token) ----
    #pragma unroll
    for (int p = 0; p < 8; p++) {
        float vv = q2p[p];
        vv += __shfl_xor_sync(0xffffffffu, vv, 8);
        vv += __shfl_xor_sync(0xffffffffu, vv, 4);
        vv += __shfl_xor_sync(0xffffffffu, vv, 2);
        vv += __shfl_xor_sync(0xffffffffu, vv, 1);
        if (kv == 0) q2_sh[p * 8 + lt] = vv;
    }
    __syncthreads();

    // ---- epilogue ----
    #pragma unroll
    for (int mt = 0; mt < 2; mt++) {
        int r0 = wm * 32 + mt * 16 + g;
        int r1 = r0 + 8;
        float m0 = (float)msk_sh[r0], m1 = (float)msk_sh[r1];
        float q20 = q2_sh[r0], q21 = q2_sh[r1];
        #pragma unroll
        for (int nt = 0; nt < 4; nt++) {
            int cc = wn * 32 + nt * 8 + kb;
            float p20 = p2_sh[cc], p21 = p2_sh[cc + 1];
            float2 o0, o1;
            o0.x = -(q20 + p20 - 2.f * acc[mt][nt][0]) * m0;
            o0.y = -(q20 + p21 - 2.f * acc[mt][nt][1]) * m0;
            o1.x = -(q21 + p20 - 2.f * acc[mt][nt][2]) * m1;
            o1.y = -(q21 + p21 - 2.f * acc[mt][nt][3]) * m1;
            *reinterpret_cast<float2*>(out + (size_t)(tok0 + r0) * NL + cc) = o0;
            *reinterpret_cast<float2*>(out + (size_t)(tok0 + r1) * NL + cc) = o1;
        }
    }
}

// ============================================================
extern "C" void kernel_launch(void* const* d_in, const int* in_sizes, int n_in,
                              void* d_out, int out_size) {
    const float* s_emb = (const float*)d_in[0];
    const int*   s_tag = (const int*)d_in[1];
    const int*   s_msk = (const int*)d_in[2];
    const float* q_emb = (const float*)d_in[3];
    const int*   q_msk = (const int*)d_in[4];
    float* out = (float*)d_out;

    k_zero<<<256, 256>>>();
    dim3 ga(32, 8);
    k_acc<<<ga, 256>>>(s_emb, s_tag, s_msk);
    k_fin<<<64, 256>>>();
    k_main<<<256, 128>>>(q_emb, q_msk, out);
}